// round 1
// baseline (speedup 1.0000x reference)
#include <cuda_runtime.h>
#include <cuda_bf16.h>

// Problem constants (HardMoe): N=8, S=2048 -> T=16384 tokens, D=O=2048, E=8, K=2
#define T_TOKENS 16384
#define DIM_D    2048
#define DIM_O    2048
#define N_EXP    8

#define BM 128
#define BN 128
#define BK 16

// ---------------- routing scratch (device globals; no allocation) ----------------
__device__ int g_top[T_TOKENS * 2];
__device__ int g_counts[N_EXP];
__device__ int g_offsets[N_EXP];
__device__ int g_cursor[N_EXP];
__device__ int g_tokens[T_TOKENS * 2];

// ---------------- init: zero counters ----------------
__global__ void init_k() {
    int i = threadIdx.x;
    if (i < N_EXP) { g_counts[i] = 0; g_cursor[i] = 0; }
}

// ---------------- gate: fp32 logits + top-2 (one warp per token) ----------------
__global__ void gate_k(const float* __restrict__ x,
                       const float* __restrict__ gw,
                       const float* __restrict__ gb) {
    int warp = (blockIdx.x * blockDim.x + threadIdx.x) >> 5;
    int lane = threadIdx.x & 31;
    if (warp >= T_TOKENS) return;
    const float* xr = x + (size_t)warp * DIM_D;

    float acc[N_EXP];
#pragma unroll
    for (int e = 0; e < N_EXP; e++) acc[e] = 0.f;

    for (int k = lane; k < DIM_D; k += 32) {
        float xv = xr[k];
        const float4* g4 = (const float4*)(gw + (size_t)k * N_EXP);
        float4 a = g4[0];
        float4 b = g4[1];
        acc[0] += xv * a.x; acc[1] += xv * a.y; acc[2] += xv * a.z; acc[3] += xv * a.w;
        acc[4] += xv * b.x; acc[5] += xv * b.y; acc[6] += xv * b.z; acc[7] += xv * b.w;
    }
#pragma unroll
    for (int e = 0; e < N_EXP; e++) {
#pragma unroll
        for (int off = 16; off; off >>= 1)
            acc[e] += __shfl_xor_sync(0xffffffffu, acc[e], off);
    }

    if (lane == 0) {
        // top-2 with jax.lax.top_k tie semantics (earlier index wins ties)
        float v1 = -1e30f, v2 = -1e30f;
        int i1 = 0, i2 = 0;
#pragma unroll
        for (int e = 0; e < N_EXP; e++) {
            float v = acc[e] + gb[e];
            if (v > v1)      { v2 = v1; i2 = i1; v1 = v; i1 = e; }
            else if (v > v2) { v2 = v;  i2 = e; }
        }
        g_top[warp * 2 + 0] = i1;
        g_top[warp * 2 + 1] = i2;
        atomicAdd(&g_counts[i1], 1);
        atomicAdd(&g_counts[i2], 1);
    }
}

// ---------------- exclusive scan over 8 counts ----------------
__global__ void scan_k() {
    if (threadIdx.x == 0) {
        int o = 0;
        for (int e = 0; e < N_EXP; e++) { g_offsets[e] = o; o += g_counts[e]; }
    }
}

// ---------------- scatter tokens into per-expert lists ----------------
__global__ void scatter_k() {
    int i = blockIdx.x * blockDim.x + threadIdx.x;
    if (i >= T_TOKENS * 2) return;
    int e = g_top[i];
    int pos = atomicAdd(&g_cursor[e], 1);
    g_tokens[g_offsets[e] + pos] = i >> 1;
}

// ---------------- grouped GEMM: out[t,:] += 0.5*relu(x[t,:] @ W_e + b_e) ----------------
__global__ __launch_bounds__(256, 2)
void moe_gemm(const float* __restrict__ x,
              const float* __restrict__ ew,
              const float* __restrict__ eb,
              float* __restrict__ out) {
    int e   = blockIdx.z;
    int cnt = g_counts[e];
    int m0  = blockIdx.y * BM;
    if (m0 >= cnt) return;
    int n0  = blockIdx.x * BN;

    __shared__ float As[BK][BM + 1];  // stride 129: conflict-free transpose stores
    __shared__ float Bs[BK][BN];
    __shared__ int   toks[BM];

    int tid = threadIdx.x;
    if (tid < BM) {
        int m = m0 + tid;
        toks[tid] = (m < cnt) ? g_tokens[g_offsets[e] + m] : -1;
    }
    __syncthreads();

    const float* We = ew + (size_t)e * DIM_D * DIM_O;

    // A-tile loader mapping: 128 rows x 16 k = 512 float4; 256 threads x 2
    int ar = tid >> 2;          // row 0..63 (and +64)
    int ak = (tid & 3) * 4;     // k quad within BK
    // B-tile loader mapping: 16 rows x 128 cols = 512 float4; 256 threads x 2
    int br = tid >> 5;          // k row 0..7 (and +8)
    int bc = (tid & 31) * 4;    // col quad

    int tx = tid & 15;          // output col group
    int ty = tid >> 4;          // output row group

    int t0 = toks[ar];
    int t1 = toks[ar + 64];

    float acc[8][8];
#pragma unroll
    for (int i = 0; i < 8; i++)
#pragma unroll
        for (int j = 0; j < 8; j++) acc[i][j] = 0.f;

    float4 aReg0, aReg1, bReg0, bReg1;
    const float4 z4 = make_float4(0.f, 0.f, 0.f, 0.f);

    // prefetch k0 = 0
    aReg0 = (t0 >= 0) ? *(const float4*)(x + (size_t)t0 * DIM_D + ak) : z4;
    aReg1 = (t1 >= 0) ? *(const float4*)(x + (size_t)t1 * DIM_D + ak) : z4;
    bReg0 = *(const float4*)(We + (size_t)br * DIM_O + n0 + bc);
    bReg1 = *(const float4*)(We + (size_t)(br + 8) * DIM_O + n0 + bc);

    for (int k0 = 0; k0 < DIM_D; k0 += BK) {
        __syncthreads();  // previous compute done before overwrite
        // transpose-store A: As[k][m]
        As[ak + 0][ar] = aReg0.x;  As[ak + 1][ar] = aReg0.y;
        As[ak + 2][ar] = aReg0.z;  As[ak + 3][ar] = aReg0.w;
        As[ak + 0][ar + 64] = aReg1.x;  As[ak + 1][ar + 64] = aReg1.y;
        As[ak + 2][ar + 64] = aReg1.z;  As[ak + 3][ar + 64] = aReg1.w;
        *(float4*)&Bs[br][bc]     = bReg0;
        *(float4*)&Bs[br + 8][bc] = bReg1;
        __syncthreads();

        int kn = k0 + BK;
        if (kn < DIM_D) {  // prefetch next slab while computing
            aReg0 = (t0 >= 0) ? *(const float4*)(x + (size_t)t0 * DIM_D + kn + ak) : z4;
            aReg1 = (t1 >= 0) ? *(const float4*)(x + (size_t)t1 * DIM_D + kn + ak) : z4;
            bReg0 = *(const float4*)(We + (size_t)(kn + br) * DIM_O + n0 + bc);
            bReg1 = *(const float4*)(We + (size_t)(kn + br + 8) * DIM_O + n0 + bc);
        }

#pragma unroll
        for (int kk = 0; kk < BK; kk++) {
            float a[8], b[8];
#pragma unroll
            for (int i = 0; i < 8; i++) a[i] = As[kk][ty * 8 + i];
            float4 b0 = *(const float4*)&Bs[kk][tx * 8];
            float4 b1 = *(const float4*)&Bs[kk][tx * 8 + 4];
            b[0] = b0.x; b[1] = b0.y; b[2] = b0.z; b[3] = b0.w;
            b[4] = b1.x; b[5] = b1.y; b[6] = b1.z; b[7] = b1.w;
#pragma unroll
            for (int i = 0; i < 8; i++)
#pragma unroll
                for (int j = 0; j < 8; j++)
                    acc[i][j] += a[i] * b[j];
        }
    }

    // epilogue: relu(acc + bias) * 0.5 -> atomicAdd into out row of token
    const float* be = eb + (size_t)e * DIM_O + n0 + tx * 8;
    float bias[8];
#pragma unroll
    for (int j = 0; j < 8; j++) bias[j] = be[j];

#pragma unroll
    for (int i = 0; i < 8; i++) {
        int t = toks[ty * 8 + i];
        if (t < 0) continue;
        float* orow = out + (size_t)t * DIM_O + n0 + tx * 8;
#pragma unroll
        for (int j = 0; j < 8; j++) {
            float v = acc[i][j] + bias[j];
            v = fmaxf(v, 0.f) * 0.5f;
            atomicAdd(orow + j, v);
        }
    }
}

// ---------------- launch ----------------
extern "C" void kernel_launch(void* const* d_in, const int* in_sizes, int n_in,
                              void* d_out, int out_size) {
    const float* x  = (const float*)d_in[0];   // [N,S,D]
    const float* gw = (const float*)d_in[1];   // [D,E]
    const float* gb = (const float*)d_in[2];   // [E]
    const float* ew = (const float*)d_in[3];   // [E,D,O]
    const float* eb = (const float*)d_in[4];   // [E,O]
    float* out = (float*)d_out;                // [N,S,O]

    init_k<<<1, 32>>>();
    gate_k<<<T_TOKENS / 8, 256>>>(x, gw, gb);
    scan_k<<<1, 1>>>();
    scatter_k<<<(T_TOKENS * 2) / 256, 256>>>();
    cudaMemsetAsync(d_out, 0, (size_t)out_size * sizeof(float));
    moe_gemm<<<dim3(DIM_O / BN, T_TOKENS / BM, N_EXP), 256>>>(x, ew, eb, out);
}

// round 3
// speedup vs baseline: 3.1993x; 3.1993x over previous
#include <cuda_runtime.h>
#include <cuda_bf16.h>
#include <cstdint>

// Problem: N=8,S=2048 -> T=16384 tokens, D=O=2048, E=8, top-2
#define T_TOKENS 16384
#define DIM_D    2048
#define DIM_O    2048
#define N_EXP    8
#define MAX_TILES 264               // ceil-per-expert padding worst case
#define R_MAX    (MAX_TILES * 128)  // 33792 padded rows

#define BM 128
#define BN 128
#define BK 32
#define AS_STRIDE 36    // floats; conflict-free A frag loads (4g+q)
#define BS_STRIDE 136   // floats; conflict-free B frag loads (8q+g)

// ---------------- device scratch (static; no allocation) ----------------
__device__ float g_operm[(size_t)R_MAX * DIM_O];  // relu(XW+b) per (token,expert) row
__device__ int g_top[T_TOKENS * 2];
__device__ int g_counts[N_EXP];
__device__ int g_offsets[N_EXP];
__device__ int g_cursor[N_EXP];
__device__ int g_rows[R_MAX];        // padded row -> token (-1 pad)
__device__ int g_pos[T_TOKENS * 2];  // (token,k) -> padded row
__device__ int g_tile_e[MAX_TILES];
__device__ int g_tile_r0[MAX_TILES];
__device__ int g_num_tiles;
__device__ int g_total_rows;

__device__ __forceinline__ float to_tf32(float v) {
    float r; asm("cvt.rna.tf32.f32 %0, %1;" : "=f"(r) : "f"(v)); return r;
}
__device__ __forceinline__ void mma_tf32(float* d, const uint32_t* a, uint32_t b0, uint32_t b1) {
    asm volatile(
        "mma.sync.aligned.m16n8k8.row.col.f32.tf32.tf32.f32 "
        "{%0,%1,%2,%3}, {%4,%5,%6,%7}, {%8,%9}, {%0,%1,%2,%3};"
        : "+f"(d[0]), "+f"(d[1]), "+f"(d[2]), "+f"(d[3])
        : "r"(a[0]), "r"(a[1]), "r"(a[2]), "r"(a[3]), "r"(b0), "r"(b1));
}

// ---------------- init ----------------
__global__ void init_k() {
    int i = threadIdx.x;
    if (i < N_EXP) { g_counts[i] = 0; g_cursor[i] = 0; }
}

// ---------------- gate: fp32 logits + top-2 (warp per token) ----------------
__global__ void gate_k(const float* __restrict__ x,
                       const float* __restrict__ gw,
                       const float* __restrict__ gb) {
    int warp = (blockIdx.x * blockDim.x + threadIdx.x) >> 5;
    int lane = threadIdx.x & 31;
    if (warp >= T_TOKENS) return;
    const float* xr = x + (size_t)warp * DIM_D;
    float acc[N_EXP];
#pragma unroll
    for (int e = 0; e < N_EXP; e++) acc[e] = 0.f;
    for (int k = lane; k < DIM_D; k += 32) {
        float xv = xr[k];
        const float4* g4 = (const float4*)(gw + (size_t)k * N_EXP);
        float4 a = g4[0], b = g4[1];
        acc[0] += xv * a.x; acc[1] += xv * a.y; acc[2] += xv * a.z; acc[3] += xv * a.w;
        acc[4] += xv * b.x; acc[5] += xv * b.y; acc[6] += xv * b.z; acc[7] += xv * b.w;
    }
#pragma unroll
    for (int e = 0; e < N_EXP; e++)
#pragma unroll
        for (int off = 16; off; off >>= 1)
            acc[e] += __shfl_xor_sync(0xffffffffu, acc[e], off);
    if (lane == 0) {
        float v1 = -1e30f, v2 = -1e30f; int i1 = 0, i2 = 0;
#pragma unroll
        for (int e = 0; e < N_EXP; e++) {
            float v = acc[e] + gb[e];
            if (v > v1)      { v2 = v1; i2 = i1; v1 = v; i1 = e; }
            else if (v > v2) { v2 = v;  i2 = e; }
        }
        g_top[warp * 2 + 0] = i1;
        g_top[warp * 2 + 1] = i2;
        atomicAdd(&g_counts[i1], 1);
        atomicAdd(&g_counts[i2], 1);
    }
}

// ---------------- scan: padded offsets + tile table ----------------
__global__ void scan_k() {
    if (threadIdx.x != 0) return;
    int o = 0, t = 0;
    for (int e = 0; e < N_EXP; e++) {
        g_offsets[e] = o;
        int nt = (g_counts[e] + 127) / 128;
        for (int i = 0; i < nt; i++) { g_tile_e[t] = e; g_tile_r0[t] = o + i * 128; t++; }
        o += nt * 128;
    }
    g_num_tiles = t;
    g_total_rows = o;
}

// ---------------- scatter ----------------
__global__ void scatter_k() {
    int i = blockIdx.x * blockDim.x + threadIdx.x;
    if (i >= T_TOKENS * 2) return;
    int e = g_top[i];
    int pos = atomicAdd(&g_cursor[e], 1);
    int row = g_offsets[e] + pos;
    g_rows[row] = i >> 1;
    g_pos[i] = row;
}

// ---------------- grouped GEMM via mma.sync tf32 ----------------
__global__ void __launch_bounds__(256, 2)
moe_mma(const float* __restrict__ x,
        const float* __restrict__ ew,
        const float* __restrict__ eb) {
    int mt = blockIdx.y;
    if (mt >= g_num_tiles) return;
    int e    = g_tile_e[mt];
    int row0 = g_tile_r0[mt];
    int n0   = blockIdx.x * BN;

    __shared__ __align__(16) float As[BM][AS_STRIDE];
    __shared__ __align__(16) float Bs[BK][BS_STRIDE];
    __shared__ int toks[BM];

    int tid = threadIdx.x;
    if (tid < BM) toks[tid] = g_rows[row0 + tid];
    __syncthreads();

    // loader mapping
    int ar = tid >> 3;           // 0..31, rows {ar, +32, +64, +96}
    int ak = (tid & 7) * 4;      // k offset 0..28
    int bk = tid >> 5;           // 0..7, rows {bk, +8, +16, +24}
    int bn = (tid & 31) * 4;     // n offset

    int tok[4];
#pragma unroll
    for (int i = 0; i < 4; i++) tok[i] = toks[ar + 32 * i];

    const float* We = ew + (size_t)e * DIM_D * DIM_O + n0;

    // warp / fragment mapping
    int warp = tid >> 5, lane = tid & 31;
    int wm = (warp & 3) * 32;    // warp rows
    int wn = (warp >> 2) * 64;   // warp cols
    int g = lane >> 2, q = lane & 3;

    float acc[2][8][4];
#pragma unroll
    for (int t = 0; t < 2; t++)
#pragma unroll
        for (int n = 0; n < 8; n++)
#pragma unroll
            for (int j = 0; j < 4; j++) acc[t][n][j] = 0.f;

    const float4 z4 = make_float4(0.f, 0.f, 0.f, 0.f);
    float4 aReg[4], bReg[4];

    // prefetch k0 = 0
#pragma unroll
    for (int i = 0; i < 4; i++)
        aReg[i] = (tok[i] >= 0) ? *(const float4*)(x + (size_t)tok[i] * DIM_D + ak) : z4;
#pragma unroll
    for (int i = 0; i < 4; i++)
        bReg[i] = *(const float4*)(We + (size_t)(bk + 8 * i) * DIM_O + bn);

    const uint32_t* Asu = (const uint32_t*)&As[0][0];
    const uint32_t* Bsu = (const uint32_t*)&Bs[0][0];

    for (int k0 = 0; k0 < DIM_D; k0 += BK) {
        __syncthreads();
        // store tiles with tf32 round-to-nearest
#pragma unroll
        for (int i = 0; i < 4; i++) {
            float4 v = aReg[i];
            v.x = to_tf32(v.x); v.y = to_tf32(v.y); v.z = to_tf32(v.z); v.w = to_tf32(v.w);
            *(float4*)&As[ar + 32 * i][ak] = v;
        }
#pragma unroll
        for (int i = 0; i < 4; i++) {
            float4 v = bReg[i];
            v.x = to_tf32(v.x); v.y = to_tf32(v.y); v.z = to_tf32(v.z); v.w = to_tf32(v.w);
            *(float4*)&Bs[bk + 8 * i][bn] = v;
        }
        __syncthreads();

        int kn = k0 + BK;
        if (kn < DIM_D) {
#pragma unroll
            for (int i = 0; i < 4; i++)
                aReg[i] = (tok[i] >= 0) ? *(const float4*)(x + (size_t)tok[i] * DIM_D + kn + ak) : z4;
#pragma unroll
            for (int i = 0; i < 4; i++)
                bReg[i] = *(const float4*)(We + (size_t)(kn + bk + 8 * i) * DIM_O + bn);
        }

#pragma unroll
        for (int j = 0; j < 4; j++) {
            int cb = j * 8;
            uint32_t a[2][4];
#pragma unroll
            for (int t = 0; t < 2; t++) {
                int r = wm + t * 16 + g;
                a[t][0] = Asu[(size_t)r * AS_STRIDE + cb + q];
                a[t][1] = Asu[(size_t)(r + 8) * AS_STRIDE + cb + q];
                a[t][2] = Asu[(size_t)r * AS_STRIDE + cb + q + 4];
                a[t][3] = Asu[(size_t)(r + 8) * AS_STRIDE + cb + q + 4];
            }
#pragma unroll
            for (int nt = 0; nt < 8; nt++) {
                int n = wn + nt * 8 + g;
                uint32_t b0 = Bsu[(size_t)(cb + q) * BS_STRIDE + n];
                uint32_t b1 = Bsu[(size_t)(cb + q + 4) * BS_STRIDE + n];
                mma_tf32(acc[0][nt], a[0], b0, b1);
                mma_tf32(acc[1][nt], a[1], b0, b1);
            }
        }
    }

    // epilogue: relu(acc + bias) -> g_operm
    const float* ebrow = eb + (size_t)e * DIM_O;
#pragma unroll
    for (int t = 0; t < 2; t++) {
#pragma unroll
        for (int nt = 0; nt < 8; nt++) {
            int col = n0 + wn + nt * 8 + 2 * q;
            float b0v = ebrow[col], b1v = ebrow[col + 1];
            int r = row0 + wm + t * 16 + g;
            float2 v0, v1;
            v0.x = fmaxf(acc[t][nt][0] + b0v, 0.f);
            v0.y = fmaxf(acc[t][nt][1] + b1v, 0.f);
            v1.x = fmaxf(acc[t][nt][2] + b0v, 0.f);
            v1.y = fmaxf(acc[t][nt][3] + b1v, 0.f);
            *(float2*)(g_operm + (size_t)r * DIM_O + col) = v0;
            *(float2*)(g_operm + (size_t)(r + 8) * DIM_O + col) = v1;
        }
    }
}

// ---------------- combine: out[t] = 0.5*(row_e1 + row_e2) ----------------
__global__ void combine_k(float* __restrict__ out) {
    int t = blockIdx.x;
    const float4* a = (const float4*)(g_operm + (size_t)g_pos[2 * t] * DIM_O);
    const float4* b = (const float4*)(g_operm + (size_t)g_pos[2 * t + 1] * DIM_O);
    float4* o = (float4*)(out + (size_t)t * DIM_O);
    for (int i = threadIdx.x; i < DIM_O / 4; i += blockDim.x) {
        float4 va = a[i], vb = b[i];
        float4 v;
        v.x = 0.5f * (va.x + vb.x); v.y = 0.5f * (va.y + vb.y);
        v.z = 0.5f * (va.z + vb.z); v.w = 0.5f * (va.w + vb.w);
        o[i] = v;
    }
}

// ---------------- host ----------------
extern "C" void kernel_launch(void* const* d_in, const int* in_sizes, int n_in,
                              void* d_out, int out_size) {
    const float* x  = (const float*)d_in[0];
    const float* gw = (const float*)d_in[1];
    const float* gb = (const float*)d_in[2];
    const float* ew = (const float*)d_in[3];
    const float* eb = (const float*)d_in[4];
    float* out = (float*)d_out;

    void* p_rows;
    cudaGetSymbolAddress(&p_rows, g_rows);

    init_k<<<1, 32>>>();
    cudaMemsetAsync(p_rows, 0xFF, R_MAX * sizeof(int));
    gate_k<<<T_TOKENS / 8, 256>>>(x, gw, gb);
    scan_k<<<1, 1>>>();
    scatter_k<<<(T_TOKENS * 2) / 256, 256>>>();
    moe_mma<<<dim3(DIM_O / BN, MAX_TILES), 256>>>(x, ew, eb);
    combine_k<<<T_TOKENS, 256>>>(out);
}